// round 9
// baseline (speedup 1.0000x reference)
#include <cuda_runtime.h>
#include <cuda_fp16.h>
#include <cstdint>

#define BATCH 4
#define SEQ   256
#define CDIM  512
#define HEADS 8
#define HDIM  64
#define BN    1024        // BATCH*SEQ
#define M2    262144      // BATCH*SEQ*SEQ

// -------- scratch (device globals; no allocation allowed) --------
__device__ float  g_Q[BN * CDIM];           // Q pre-scaled by 1/sqrt(D)=1/8
__device__ float  g_K[BN * CDIM];
__device__ float  g_V[BN * CDIM];
__device__ __half g_WeTh[CDIM * CDIM];      // We transposed [n][k], fp16
__device__ float  g_S[(size_t)M2 * HEADS];  // per-head score sums [B,N,N,H]

// ==================== PTX helpers (sm_103 baseline ISA) ====================
__device__ __forceinline__ unsigned f2tf(float x) {
    unsigned u;
    asm("cvt.rna.tf32.f32 %0, %1;" : "=r"(u) : "f"(x));
    return u;
}

__device__ __forceinline__ void mma8(float* c,
                                     unsigned a0, unsigned a1, unsigned a2, unsigned a3,
                                     unsigned b0, unsigned b1) {
    asm volatile(
        "mma.sync.aligned.m16n8k8.row.col.f32.tf32.tf32.f32 "
        "{%0,%1,%2,%3},{%4,%5,%6,%7},{%8,%9},{%0,%1,%2,%3};"
        : "+f"(c[0]), "+f"(c[1]), "+f"(c[2]), "+f"(c[3])
        : "r"(a0), "r"(a1), "r"(a2), "r"(a3), "r"(b0), "r"(b1));
}

__device__ __forceinline__ void mmah(float* c,
                                     unsigned a0, unsigned a1, unsigned a2, unsigned a3,
                                     unsigned b0, unsigned b1) {
    asm volatile(
        "mma.sync.aligned.m16n8k16.row.col.f32.f16.f16.f32 "
        "{%0,%1,%2,%3},{%4,%5,%6,%7},{%8,%9},{%0,%1,%2,%3};"
        : "+f"(c[0]), "+f"(c[1]), "+f"(c[2]), "+f"(c[3])
        : "r"(a0), "r"(a1), "r"(a2), "r"(a3), "r"(b0), "r"(b1));
}

__device__ __forceinline__ void ldsm4(unsigned& r0, unsigned& r1, unsigned& r2, unsigned& r3,
                                      uint32_t addr) {
    asm volatile("ldmatrix.sync.aligned.m8n8.x4.shared.b16 {%0,%1,%2,%3}, [%4];"
                 : "=r"(r0), "=r"(r1), "=r"(r2), "=r"(r3) : "r"(addr));
}

__device__ __forceinline__ void cp16(void* s, const void* g) {
    unsigned ss = (unsigned)__cvta_generic_to_shared(s);
    asm volatile("cp.async.cg.shared.global [%0], [%1], 16;" :: "r"(ss), "l"(g));
}
__device__ __forceinline__ void cp_commit() { asm volatile("cp.async.commit_group;"); }
template <int N>
__device__ __forceinline__ void cp_wait() { asm volatile("cp.async.wait_group %0;" :: "n"(N)); }

__device__ __forceinline__ uint32_t smem_u32(const void* p) {
    uint32_t a;
    asm("{ .reg .u64 t; cvta.to.shared.u64 t, %1; cvt.u32.u64 %0, t; }" : "=r"(a) : "l"(p));
    return a;
}

// =====================================================================
// Prep: g_WeTh[n][k] = fp16(We[k][n])  (512x512 transpose + convert)
// =====================================================================
__global__ __launch_bounds__(256) void prep_weT_kernel(const float* __restrict__ We)
{
    __shared__ float t[32][33];
    int k0 = blockIdx.x * 32, n0 = blockIdx.y * 32;
    int tx = threadIdx.x & 31, ty = threadIdx.x >> 5;
    #pragma unroll
    for (int yy = 0; yy < 4; yy++) {
        int k = ty + yy * 8;
        t[k][tx] = We[(size_t)(k0 + k) * 512 + n0 + tx];
    }
    __syncthreads();
    #pragma unroll
    for (int yy = 0; yy < 4; yy++) {
        int n = ty + yy * 8;
        g_WeTh[(size_t)(n0 + n) * 512 + k0 + tx] = __float2half_rn(t[tx][n]);
    }
}

// =====================================================================
// Pass 1: Q/K/V projections, split-tf32 (3-mma) for ~fp32 accuracy.
// =====================================================================
__global__ __launch_bounds__(128) void qkv_kernel(
    const float* __restrict__ hmat,
    const float* __restrict__ Wq,
    const float* __restrict__ Wk,
    const float* __restrict__ Wv)
{
    __shared__ float Ah[64][36], Al[64][36];
    __shared__ float Bh[32][72], Bl[32][72];

    int z = blockIdx.z;
    const float* W = (z == 0) ? Wq : ((z == 1) ? Wk : Wv);
    float* Out = (z == 0) ? g_Q : ((z == 1) ? g_K : g_V);
    float scale = (z == 0) ? 0.125f : 1.0f;

    int m0 = blockIdx.x * 64, n0 = blockIdx.y * 64;
    int tid = threadIdx.x;
    int w = tid >> 5, lane = tid & 31, g = lane >> 2, q = lane & 3;
    int wr = (w >> 1) * 32, wc = (w & 1) * 32;

    float acc[2][4][4] = {};

    for (int k0 = 0; k0 < 512; k0 += 32) {
        #pragma unroll
        for (int it = 0; it < 4; it++) {
            int f = tid + it * 128;
            int r = f >> 3, c4 = (f & 7) * 4;
            float4 x = *(const float4*)(hmat + (size_t)(m0 + r) * 512 + k0 + c4);
            float hx = __uint_as_float(f2tf(x.x));
            float hy = __uint_as_float(f2tf(x.y));
            float hz = __uint_as_float(f2tf(x.z));
            float hw = __uint_as_float(f2tf(x.w));
            Ah[r][c4 + 0] = hx; Ah[r][c4 + 1] = hy; Ah[r][c4 + 2] = hz; Ah[r][c4 + 3] = hw;
            Al[r][c4 + 0] = __uint_as_float(f2tf(x.x - hx));
            Al[r][c4 + 1] = __uint_as_float(f2tf(x.y - hy));
            Al[r][c4 + 2] = __uint_as_float(f2tf(x.z - hz));
            Al[r][c4 + 3] = __uint_as_float(f2tf(x.w - hw));
        }
        #pragma unroll
        for (int it = 0; it < 4; it++) {
            int f = tid + it * 128;
            int k = f >> 4, c4 = (f & 15) * 4;
            float4 x = *(const float4*)(W + (size_t)(k0 + k) * 512 + n0 + c4);
            float hx = __uint_as_float(f2tf(x.x));
            float hy = __uint_as_float(f2tf(x.y));
            float hz = __uint_as_float(f2tf(x.z));
            float hw = __uint_as_float(f2tf(x.w));
            Bh[k][c4 + 0] = hx; Bh[k][c4 + 1] = hy; Bh[k][c4 + 2] = hz; Bh[k][c4 + 3] = hw;
            Bl[k][c4 + 0] = __uint_as_float(f2tf(x.x - hx));
            Bl[k][c4 + 1] = __uint_as_float(f2tf(x.y - hy));
            Bl[k][c4 + 2] = __uint_as_float(f2tf(x.z - hz));
            Bl[k][c4 + 3] = __uint_as_float(f2tf(x.w - hw));
        }
        __syncthreads();

        #pragma unroll
        for (int kt = 0; kt < 4; kt++) {
            unsigned ah[2][4], al[2][4];
            #pragma unroll
            for (int m = 0; m < 2; m++) {
                int r = wr + m * 16 + g;
                int kk = kt * 8 + q;
                ah[m][0] = __float_as_uint(Ah[r][kk]);
                ah[m][1] = __float_as_uint(Ah[r + 8][kk]);
                ah[m][2] = __float_as_uint(Ah[r][kk + 4]);
                ah[m][3] = __float_as_uint(Ah[r + 8][kk + 4]);
                al[m][0] = __float_as_uint(Al[r][kk]);
                al[m][1] = __float_as_uint(Al[r + 8][kk]);
                al[m][2] = __float_as_uint(Al[r][kk + 4]);
                al[m][3] = __float_as_uint(Al[r + 8][kk + 4]);
            }
            unsigned bh[4][2], bl[4][2];
            #pragma unroll
            for (int nt = 0; nt < 4; nt++) {
                int cc = wc + nt * 8 + g;
                bh[nt][0] = __float_as_uint(Bh[kt * 8 + q][cc]);
                bh[nt][1] = __float_as_uint(Bh[kt * 8 + q + 4][cc]);
                bl[nt][0] = __float_as_uint(Bl[kt * 8 + q][cc]);
                bl[nt][1] = __float_as_uint(Bl[kt * 8 + q + 4][cc]);
            }
            #pragma unroll
            for (int m = 0; m < 2; m++)
                #pragma unroll
                for (int nt = 0; nt < 4; nt++) {
                    mma8(acc[m][nt], ah[m][0], ah[m][1], ah[m][2], ah[m][3], bh[nt][0], bh[nt][1]);
                    mma8(acc[m][nt], ah[m][0], ah[m][1], ah[m][2], ah[m][3], bl[nt][0], bl[nt][1]);
                    mma8(acc[m][nt], al[m][0], al[m][1], al[m][2], al[m][3], bh[nt][0], bh[nt][1]);
                }
        }
        __syncthreads();
    }

    #pragma unroll
    for (int m = 0; m < 2; m++) {
        int r0 = m0 + wr + m * 16 + g;
        #pragma unroll
        for (int nt = 0; nt < 4; nt++) {
            int c0 = n0 + wc + nt * 8 + 2 * q;
            *(float2*)(Out + (size_t)r0 * 512 + c0) =
                make_float2(acc[m][nt][0] * scale, acc[m][nt][1] * scale);
            *(float2*)(Out + (size_t)(r0 + 8) * 512 + c0) =
                make_float2(acc[m][nt][2] * scale, acc[m][nt][3] * scale);
        }
    }
}

// =====================================================================
// Pass 2 (fp16 HMMA, persistent-A): pe = e @ We, fused epilogue.
// One CTA owns 128 m-rows x full n=512. e tile (128x512) converted to
// fp16 once into resident smem (row stride 1040B, ldsm conflict-free).
// Two n-slabs of 256; per slab: 16 K-chunks (k32), B (fp16 We^T) double-
// buffered via cp.async (row stride 80B). Warp grid 2x4, warp tile 64x64.
// Epilogue per 128x128 phase: acc -> smem stage (aliases B buffers) ->
// val = pe*q*k -> coalesced e_out store + per-head row sums into g_S.
// grid=2048, block=256.
// =====================================================================
#define A_STRIDE  1040
#define A_BYTES   (128 * A_STRIDE)        // 133120
#define B_STRIDE  80
#define B_BUF     (256 * B_STRIDE)        // 20480
#define B0_OFF    A_BYTES
#define B1_OFF    (A_BYTES + B_BUF)
#define EPI_OFF   A_BYTES                 // aliases B buffers (safe: B is per-chunk)
#define EPI_STR   132
#define PE_SMEM   (A_BYTES + 128 * EPI_STR * 4)   // 200704

__global__ __launch_bounds__(256) void pe_fp16_kernel(
    const float* __restrict__ e,
    float* __restrict__ out_e)
{
    extern __shared__ char smem[];
    uint32_t sb = smem_u32(smem);

    int tid = threadIdx.x;
    int w = tid >> 5, lane = tid & 31, g = lane >> 2, q = lane & 3;
    int wr = (w >> 2) * 64;      // warp m-offset: 0 or 64
    int wcq = w & 3;             // warp n-quarter within 256-slab

    int m0 = blockIdx.x * 128;
    int b = m0 >> 16;
    int i = (m0 >> 8) & 255;
    int j0 = m0 & 255;
    int bi = b * 256 + i;
    int b256 = b * 256;

    // ---- stage A: e[m0..m0+127][0..511] -> fp16 smem, row stride 1040B ----
    #pragma unroll 4
    for (int it = 0; it < 64; it++) {
        int f = tid + it * 256;
        int r = f >> 7, c = f & 127;          // c = float4 index in row
        float4 x = *(const float4*)(e + (size_t)(m0 + r) * 512 + c * 4);
        __half2 h0 = __floats2half2_rn(x.x, x.y);
        __half2 h1 = __floats2half2_rn(x.z, x.w);
        *(uint2*)(smem + r * A_STRIDE + c * 8) =
            make_uint2(*(unsigned*)&h0, *(unsigned*)&h1);
    }

    // per-lane ldmatrix address components
    uint32_t a_base = sb + (uint32_t)((wr + (lane & 15)) * A_STRIDE + (lane >> 4) * 16);
    uint32_t b_lane = (uint32_t)(((lane & 7) + ((lane >> 4) << 3)) * B_STRIDE
                                 + ((lane >> 3) & 1) * 16);

    #pragma unroll 1
    for (int slab = 0; slab < 2; slab++) {
        int ns = slab * 256;
        const __half* wsrc = g_WeTh + (size_t)ns * 512;
        float acc[4][8][4] = {};

        __syncthreads();   // A staged (slab0) / epilogue done (slab1)

        // prologue: B chunk 0 -> buf0
        {
            #pragma unroll
            for (int it = 0; it < 4; it++) {
                int idx = tid + it * 256;
                int n = idx >> 2, seg = idx & 3;
                cp16(smem + B0_OFF + n * B_STRIDE + seg * 16,
                     wsrc + (size_t)n * 512 + seg * 8);
            }
            cp_commit();
        }

        for (int kc = 0; kc < 16; kc++) {
            int p = kc & 1;
            if (kc < 15) {
                int boff = p ? B0_OFF : B1_OFF;
                #pragma unroll
                for (int it = 0; it < 4; it++) {
                    int idx = tid + it * 256;
                    int n = idx >> 2, seg = idx & 3;
                    cp16(smem + boff + n * B_STRIDE + seg * 16,
                         wsrc + (size_t)n * 512 + (kc + 1) * 32 + seg * 8);
                }
                cp_commit();
                cp_wait<1>();
            } else {
                cp_wait<0>();
            }
            __syncthreads();

            uint32_t Bb = sb + (p ? B1_OFF : B0_OFF) + wcq * 64 * B_STRIDE + b_lane;
            uint32_t Aa = a_base + kc * 64;
            #pragma unroll
            for (int kt = 0; kt < 2; kt++) {
                unsigned bb[4][4];
                #pragma unroll
                for (int nt = 0; nt < 4; nt++)
                    ldsm4(bb[nt][0], bb[nt][1], bb[nt][2], bb[nt][3],
                          Bb + nt * (16 * B_STRIDE) + kt * 32);
                #pragma unroll
                for (int mt = 0; mt < 4; mt++) {
                    unsigned a0, a1, a2, a3;
                    ldsm4(a0, a1, a2, a3, Aa + mt * (16 * A_STRIDE) + kt * 32);
                    #pragma unroll
                    for (int nt = 0; nt < 4; nt++) {
                        mmah(acc[mt][2 * nt],     a0, a1, a2, a3, bb[nt][0], bb[nt][1]);
                        mmah(acc[mt][2 * nt + 1], a0, a1, a2, a3, bb[nt][2], bb[nt][3]);
                    }
                }
            }
            __syncthreads();   // mma(p) done before buf p is refilled next iter
        }

        // ---- epilogue: two 128x128 phases staged through smem ----
        float* epi = (float*)(smem + EPI_OFF);
        #pragma unroll 1
        for (int p = 0; p < 2; p++) {
            if ((wcq >> 1) == p) {
                int ch = (wcq & 1) * 64;
                #pragma unroll
                for (int mt = 0; mt < 4; mt++) {
                    int rr = wr + mt * 16 + g;
                    #pragma unroll
                    for (int nt = 0; nt < 8; nt++) {
                        int pc = ch + nt * 8 + 2 * q;
                        *(float2*)(epi + (size_t)rr * EPI_STR + pc) =
                            make_float2(acc[mt][nt][0], acc[mt][nt][1]);
                        *(float2*)(epi + (size_t)(rr + 8) * EPI_STR + pc) =
                            make_float2(acc[mt][nt][2], acc[mt][nt][3]);
                    }
                }
            }
            __syncthreads();

            int colg = ns + p * 128 + lane * 4;
            float4 q4 = *(const float4*)(g_Q + (size_t)bi * 512 + colg);
            int head = slab * 4 + p * 2 + (lane >> 4);
            #pragma unroll 4
            for (int it = 0; it < 16; it++) {
                int r = w + it * 8;
                float4 p4 = *(const float4*)(epi + (size_t)r * EPI_STR + lane * 4);
                float4 k4 = *(const float4*)(g_K + (size_t)(b256 + j0 + r) * 512 + colg);
                float v0 = p4.x * q4.x * k4.x;
                float v1 = p4.y * q4.y * k4.y;
                float v2 = p4.z * q4.z * k4.z;
                float v3 = p4.w * q4.w * k4.w;
                *(float4*)(out_e + (size_t)(m0 + r) * 512 + colg) =
                    make_float4(v0, v1, v2, v3);
                float s = (v0 + v1) + (v2 + v3);
                s += __shfl_xor_sync(0xffffffffu, s, 1);
                s += __shfl_xor_sync(0xffffffffu, s, 2);
                s += __shfl_xor_sync(0xffffffffu, s, 4);
                s += __shfl_xor_sync(0xffffffffu, s, 8);
                if ((lane & 15) == 0)
                    g_S[((size_t)bi * 256 + j0 + r) * 8 + head] = s;
            }
            __syncthreads();
        }
    }
}

// =====================================================================
// Pass 3: per (b,i,h): softmax_j(clip(S, -5, 5)), then h_out = w @ V.
// =====================================================================
__global__ __launch_bounds__(256) void softmax_av_kernel(float* __restrict__ out_h)
{
    __shared__ float ws[256];
    __shared__ float wsum[8];
    __shared__ float pacc[4][64];

    int bid = blockIdx.x;
    int hh = bid & 7;
    int bi = bid >> 3;
    int b256 = (bi >> 8) << 8;

    int tid = threadIdx.x;
    int wid = tid >> 5, lane = tid & 31;

    float sv = g_S[(size_t)bi * 2048 + (size_t)tid * 8 + hh];
    sv = fminf(5.f, fmaxf(-5.f, sv));
    float ex = expf(sv);
    ws[tid] = ex;

    float v = ex;
    #pragma unroll
    for (int o = 16; o; o >>= 1) v += __shfl_xor_sync(0xffffffffu, v, o);
    if (lane == 0) wsum[wid] = v;
    __syncthreads();

    float tot = 0.f;
    #pragma unroll
    for (int x = 0; x < 8; x++) tot += wsum[x];
    float inv = 1.f / tot;

    int d = tid & 63, part = tid >> 6;
    const float* Vb = g_V + (size_t)b256 * 512 + hh * 64 + d;
    float a = 0.f;
    int jbase = part * 64;
    #pragma unroll 4
    for (int j = 0; j < 64; j++)
        a += ws[jbase + j] * Vb[(size_t)(jbase + j) * 512];
    pacc[part][d] = a;
    __syncthreads();

    if (part == 0) {
        float r = (pacc[0][d] + pacc[1][d] + pacc[2][d] + pacc[3][d]) * inv;
        out_h[(size_t)bi * 512 + hh * 64 + d] = r;
    }
}

// =====================================================================
extern "C" void kernel_launch(void* const* d_in, const int* in_sizes, int n_in,
                              void* d_out, int out_size)
{
    const float* h  = (const float*)d_in[0];
    const float* e  = (const float*)d_in[1];
    const float* Wq = (const float*)d_in[2];
    const float* Wk = (const float*)d_in[3];
    const float* Wv = (const float*)d_in[4];
    const float* We = (const float*)d_in[5];

    float* out = (float*)d_out;
    float* out_h = out;                              // [4,256,512]
    float* out_e = out + (size_t)BN * CDIM;          // [4,256,256,512]

    dim3 gp(16, 16);
    prep_weT_kernel<<<gp, 256>>>(We);

    dim3 g1(16, 8, 3);
    qkv_kernel<<<g1, 128>>>(h, Wq, Wk, Wv);

    cudaFuncSetAttribute(pe_fp16_kernel, cudaFuncAttributeMaxDynamicSharedMemorySize, PE_SMEM);
    pe_fp16_kernel<<<2048, 256, PE_SMEM>>>(e, out_e);

    softmax_av_kernel<<<8192, 256>>>(out_h);
}

// round 12
// speedup vs baseline: 1.2668x; 1.2668x over previous
#include <cuda_runtime.h>
#include <cuda_fp16.h>
#include <cstdint>

#define BATCH 4
#define SEQ   256
#define CDIM  512
#define HEADS 8
#define HDIM  64
#define BN    1024        // BATCH*SEQ
#define M2    262144      // BATCH*SEQ*SEQ

// -------- scratch (device globals; no allocation allowed) --------
__device__ float  g_Q[BN * CDIM];           // Q pre-scaled by 1/sqrt(D)=1/8
__device__ float  g_K[BN * CDIM];
__device__ float  g_V[BN * CDIM];
__device__ __half g_WeTh[CDIM * CDIM];      // We transposed [n][k], fp16
__device__ float  g_S[(size_t)M2 * HEADS];  // per-head score sums [B,N,N,H]

// ==================== PTX helpers (sm_103 baseline ISA) ====================
__device__ __forceinline__ unsigned f2tf(float x) {
    unsigned u;
    asm("cvt.rna.tf32.f32 %0, %1;" : "=r"(u) : "f"(x));
    return u;
}

__device__ __forceinline__ void mma8(float* c,
                                     unsigned a0, unsigned a1, unsigned a2, unsigned a3,
                                     unsigned b0, unsigned b1) {
    asm volatile(
        "mma.sync.aligned.m16n8k8.row.col.f32.tf32.tf32.f32 "
        "{%0,%1,%2,%3},{%4,%5,%6,%7},{%8,%9},{%0,%1,%2,%3};"
        : "+f"(c[0]), "+f"(c[1]), "+f"(c[2]), "+f"(c[3])
        : "r"(a0), "r"(a1), "r"(a2), "r"(a3), "r"(b0), "r"(b1));
}

__device__ __forceinline__ void mmah(float* c,
                                     unsigned a0, unsigned a1, unsigned a2, unsigned a3,
                                     unsigned b0, unsigned b1) {
    asm volatile(
        "mma.sync.aligned.m16n8k16.row.col.f32.f16.f16.f32 "
        "{%0,%1,%2,%3},{%4,%5,%6,%7},{%8,%9},{%0,%1,%2,%3};"
        : "+f"(c[0]), "+f"(c[1]), "+f"(c[2]), "+f"(c[3])
        : "r"(a0), "r"(a1), "r"(a2), "r"(a3), "r"(b0), "r"(b1));
}

__device__ __forceinline__ void ldsm4(unsigned& r0, unsigned& r1, unsigned& r2, unsigned& r3,
                                      uint32_t addr) {
    asm volatile("ldmatrix.sync.aligned.m8n8.x4.shared.b16 {%0,%1,%2,%3}, [%4];"
                 : "=r"(r0), "=r"(r1), "=r"(r2), "=r"(r3) : "r"(addr));
}

__device__ __forceinline__ void cp16(void* s, const void* g) {
    unsigned ss = (unsigned)__cvta_generic_to_shared(s);
    asm volatile("cp.async.cg.shared.global [%0], [%1], 16;" :: "r"(ss), "l"(g));
}
__device__ __forceinline__ void cp_commit() { asm volatile("cp.async.commit_group;"); }
template <int N>
__device__ __forceinline__ void cp_wait() { asm volatile("cp.async.wait_group %0;" :: "n"(N)); }

__device__ __forceinline__ uint32_t smem_u32(const void* p) {
    uint32_t a;
    asm("{ .reg .u64 t; cvta.to.shared.u64 t, %1; cvt.u32.u64 %0, t; }" : "=r"(a) : "l"(p));
    return a;
}

// =====================================================================
// Prep: g_WeTh[n][k] = fp16(We[k][n])  (512x512 transpose + convert)
// =====================================================================
__global__ __launch_bounds__(256) void prep_weT_kernel(const float* __restrict__ We)
{
    __shared__ float t[32][33];
    int k0 = blockIdx.x * 32, n0 = blockIdx.y * 32;
    int tx = threadIdx.x & 31, ty = threadIdx.x >> 5;
    #pragma unroll
    for (int yy = 0; yy < 4; yy++) {
        int k = ty + yy * 8;
        t[k][tx] = We[(size_t)(k0 + k) * 512 + n0 + tx];
    }
    __syncthreads();
    #pragma unroll
    for (int yy = 0; yy < 4; yy++) {
        int n = ty + yy * 8;
        g_WeTh[(size_t)(n0 + n) * 512 + k0 + tx] = __float2half_rn(t[tx][n]);
    }
}

// =====================================================================
// Pass 1: Q/K/V projections, split-tf32 (3-mma) for ~fp32 accuracy.
// =====================================================================
__global__ __launch_bounds__(128) void qkv_kernel(
    const float* __restrict__ hmat,
    const float* __restrict__ Wq,
    const float* __restrict__ Wk,
    const float* __restrict__ Wv)
{
    __shared__ float Ah[64][36], Al[64][36];
    __shared__ float Bh[32][72], Bl[32][72];

    int z = blockIdx.z;
    const float* W = (z == 0) ? Wq : ((z == 1) ? Wk : Wv);
    float* Out = (z == 0) ? g_Q : ((z == 1) ? g_K : g_V);
    float scale = (z == 0) ? 0.125f : 1.0f;

    int m0 = blockIdx.x * 64, n0 = blockIdx.y * 64;
    int tid = threadIdx.x;
    int w = tid >> 5, lane = tid & 31, g = lane >> 2, q = lane & 3;
    int wr = (w >> 1) * 32, wc = (w & 1) * 32;

    float acc[2][4][4] = {};

    for (int k0 = 0; k0 < 512; k0 += 32) {
        #pragma unroll
        for (int it = 0; it < 4; it++) {
            int f = tid + it * 128;
            int r = f >> 3, c4 = (f & 7) * 4;
            float4 x = *(const float4*)(hmat + (size_t)(m0 + r) * 512 + k0 + c4);
            float hx = __uint_as_float(f2tf(x.x));
            float hy = __uint_as_float(f2tf(x.y));
            float hz = __uint_as_float(f2tf(x.z));
            float hw = __uint_as_float(f2tf(x.w));
            Ah[r][c4 + 0] = hx; Ah[r][c4 + 1] = hy; Ah[r][c4 + 2] = hz; Ah[r][c4 + 3] = hw;
            Al[r][c4 + 0] = __uint_as_float(f2tf(x.x - hx));
            Al[r][c4 + 1] = __uint_as_float(f2tf(x.y - hy));
            Al[r][c4 + 2] = __uint_as_float(f2tf(x.z - hz));
            Al[r][c4 + 3] = __uint_as_float(f2tf(x.w - hw));
        }
        #pragma unroll
        for (int it = 0; it < 4; it++) {
            int f = tid + it * 128;
            int k = f >> 4, c4 = (f & 15) * 4;
            float4 x = *(const float4*)(W + (size_t)(k0 + k) * 512 + n0 + c4);
            float hx = __uint_as_float(f2tf(x.x));
            float hy = __uint_as_float(f2tf(x.y));
            float hz = __uint_as_float(f2tf(x.z));
            float hw = __uint_as_float(f2tf(x.w));
            Bh[k][c4 + 0] = hx; Bh[k][c4 + 1] = hy; Bh[k][c4 + 2] = hz; Bh[k][c4 + 3] = hw;
            Bl[k][c4 + 0] = __uint_as_float(f2tf(x.x - hx));
            Bl[k][c4 + 1] = __uint_as_float(f2tf(x.y - hy));
            Bl[k][c4 + 2] = __uint_as_float(f2tf(x.z - hz));
            Bl[k][c4 + 3] = __uint_as_float(f2tf(x.w - hw));
        }
        __syncthreads();

        #pragma unroll
        for (int kt = 0; kt < 4; kt++) {
            unsigned ah[2][4], al[2][4];
            #pragma unroll
            for (int m = 0; m < 2; m++) {
                int r = wr + m * 16 + g;
                int kk = kt * 8 + q;
                ah[m][0] = __float_as_uint(Ah[r][kk]);
                ah[m][1] = __float_as_uint(Ah[r + 8][kk]);
                ah[m][2] = __float_as_uint(Ah[r][kk + 4]);
                ah[m][3] = __float_as_uint(Ah[r + 8][kk + 4]);
                al[m][0] = __float_as_uint(Al[r][kk]);
                al[m][1] = __float_as_uint(Al[r + 8][kk]);
                al[m][2] = __float_as_uint(Al[r][kk + 4]);
                al[m][3] = __float_as_uint(Al[r + 8][kk + 4]);
            }
            unsigned bh[4][2], bl[4][2];
            #pragma unroll
            for (int nt = 0; nt < 4; nt++) {
                int cc = wc + nt * 8 + g;
                bh[nt][0] = __float_as_uint(Bh[kt * 8 + q][cc]);
                bh[nt][1] = __float_as_uint(Bh[kt * 8 + q + 4][cc]);
                bl[nt][0] = __float_as_uint(Bl[kt * 8 + q][cc]);
                bl[nt][1] = __float_as_uint(Bl[kt * 8 + q + 4][cc]);
            }
            #pragma unroll
            for (int m = 0; m < 2; m++)
                #pragma unroll
                for (int nt = 0; nt < 4; nt++) {
                    mma8(acc[m][nt], ah[m][0], ah[m][1], ah[m][2], ah[m][3], bh[nt][0], bh[nt][1]);
                    mma8(acc[m][nt], ah[m][0], ah[m][1], ah[m][2], ah[m][3], bl[nt][0], bl[nt][1]);
                    mma8(acc[m][nt], al[m][0], al[m][1], al[m][2], al[m][3], bh[nt][0], bh[nt][1]);
                }
        }
        __syncthreads();
    }

    #pragma unroll
    for (int m = 0; m < 2; m++) {
        int r0 = m0 + wr + m * 16 + g;
        #pragma unroll
        for (int nt = 0; nt < 4; nt++) {
            int c0 = n0 + wc + nt * 8 + 2 * q;
            *(float2*)(Out + (size_t)r0 * 512 + c0) =
                make_float2(acc[m][nt][0] * scale, acc[m][nt][1] * scale);
            *(float2*)(Out + (size_t)(r0 + 8) * 512 + c0) =
                make_float2(acc[m][nt][2] * scale, acc[m][nt][3] * scale);
        }
    }
}

// =====================================================================
// Pass 2 (fp16 HMMA, R8 structure + fp16 + L2-friendly grid):
// pe = e @ We, CTA tile 128(m) x 128(n), K-chunk 32, double-buffered:
//   B (fp16 We^T) via cp.async; A (e) via reg-staged LDG -> cvt fp16 ->
//   STS (prefetched across the MMA). Rows 80B (16B-aligned, ldsm
//   conflict-free: r*5 mod 8 is a permutation). Warp grid 2(m)x4(n),
//   warp tile 64x32, m16n8k16.
// grid=(4, 2048): the 4 n-CTAs of one m-tile are launch-adjacent ->
//   e read from DRAM once, 3 L2 hits.
// Epilogue: two 64-row phases staged through smem (aliases buffers) ->
//   val = pe*q*k -> coalesced e_out store + per-head row sums into g_S.
// Static smem 40KB -> 2 CTAs/SM.
// =====================================================================
#define PA_STR  80
#define PA_BUF  (128 * PA_STR)      // 10240
#define PB_OFF  (2 * PA_BUF)        // 20480
#define PE_SMEM (4 * PA_BUF)        // 40960
#define EPI_STR 132                 // 64*132*4 = 33792 <= 40960 (aliases)

__global__ __launch_bounds__(256, 2) void pe_fp16_kernel(
    const float* __restrict__ e,
    float* __restrict__ out_e)
{
    __shared__ alignas(128) char smem[PE_SMEM];
    uint32_t sb = smem_u32(smem);

    int tid = threadIdx.x;
    int w = tid >> 5, lane = tid & 31, g = lane >> 2, q = lane & 3;
    int wm = (w >> 2) * 64;     // warp m-offset: 0 or 64
    int wn = (w & 3) * 32;      // warp n-offset: 0,32,64,96

    int n0 = blockIdx.x * 128;
    int m0 = blockIdx.y * 128;
    int b = m0 >> 16;
    int i = (m0 >> 8) & 255;
    int j0 = m0 & 255;
    int bi = b * 256 + i;
    int b256 = b * 256;

    // staging coords: thread -> (row, half-row of 16 floats)
    int sr = tid >> 1, sh = tid & 1;
    const float* esrc = e + (size_t)(m0 + sr) * 512 + sh * 16;
    const __half* wsrc = g_WeTh + (size_t)n0 * 512;

    // shared ldsm lane addressing: (lane&15)=row-in-16, (lane>>4)=k-half(16B)
    uint32_t lbase = sb + (uint32_t)((lane & 15) * PA_STR + (lane >> 4) * 16);

    float acc[4][4][4] = {};
    float4 av[4];

    auto Bload = [&](int kc, int p) {
        char* dst = smem + PB_OFF + p * PA_BUF;
        #pragma unroll
        for (int it = 0; it < 2; it++) {
            int idx = tid + it * 256;
            int n = idx >> 2, seg = idx & 3;
            cp16(dst + n * PA_STR + seg * 16,
                 wsrc + (size_t)n * 512 + kc * 32 + seg * 8);
        }
        cp_commit();
    };
    auto Aload = [&](int kc) {
        const float4* s4 = (const float4*)(esrc + kc * 32);
        av[0] = s4[0]; av[1] = s4[1]; av[2] = s4[2]; av[3] = s4[3];
    };
    auto Astore = [&](int p) {
        char* dst = smem + p * PA_BUF + sr * PA_STR + sh * 32;
        unsigned h[8];
        #pragma unroll
        for (int t = 0; t < 4; t++) {
            __half2 lo = __floats2half2_rn(av[t].x, av[t].y);
            __half2 hi = __floats2half2_rn(av[t].z, av[t].w);
            h[2 * t] = *(unsigned*)&lo;
            h[2 * t + 1] = *(unsigned*)&hi;
        }
        *(uint4*)dst        = make_uint4(h[0], h[1], h[2], h[3]);
        *(uint4*)(dst + 16) = make_uint4(h[4], h[5], h[6], h[7]);
    };
    auto domma = [&](int p) {
        uint32_t Ab = lbase + p * PA_BUF + wm * PA_STR;
        uint32_t Bb = lbase + PB_OFF + p * PA_BUF + wn * PA_STR;
        #pragma unroll
        for (int kt = 0; kt < 2; kt++) {
            unsigned bf[2][4];
            #pragma unroll
            for (int pr = 0; pr < 2; pr++)
                ldsm4(bf[pr][0], bf[pr][1], bf[pr][2], bf[pr][3],
                      Bb + pr * (16 * PA_STR) + kt * 32);
            #pragma unroll
            for (int mt = 0; mt < 4; mt++) {
                unsigned a0, a1, a2, a3;
                ldsm4(a0, a1, a2, a3, Ab + mt * (16 * PA_STR) + kt * 32);
                mmah(acc[mt][0], a0, a1, a2, a3, bf[0][0], bf[0][2]);
                mmah(acc[mt][1], a0, a1, a2, a3, bf[0][1], bf[0][3]);
                mmah(acc[mt][2], a0, a1, a2, a3, bf[1][0], bf[1][2]);
                mmah(acc[mt][3], a0, a1, a2, a3, bf[1][1], bf[1][3]);
            }
        }
    };

    // prologue: chunk 0
    Bload(0, 0);
    Aload(0);
    Astore(0);
    cp_wait<0>();
    __syncthreads();

    for (int kc = 0; kc < 16; kc++) {
        int p = kc & 1;
        if (kc < 15) {
            Bload(kc + 1, 1 - p);
            Aload(kc + 1);
        }
        domma(p);
        if (kc < 15) {
            Astore(1 - p);
            cp_wait<0>();
        }
        __syncthreads();
    }

    // ---- epilogue: two 64-row phases staged through smem ----
    float* epi = (float*)smem;
    float4 q4 = *(const float4*)(g_Q + (size_t)bi * 512 + n0 + (lane & 31) * 4);
    int head = (n0 >> 6) + (lane >> 4);

    #pragma unroll 1
    for (int ph = 0; ph < 2; ph++) {
        if (wm == ph * 64) {
            #pragma unroll
            for (int mt = 0; mt < 4; mt++) {
                int rr = mt * 16 + g;
                #pragma unroll
                for (int nt = 0; nt < 4; nt++) {
                    int pc = wn + nt * 8 + 2 * q;
                    *(float2*)(epi + (size_t)rr * EPI_STR + pc) =
                        make_float2(acc[mt][nt][0], acc[mt][nt][1]);
                    *(float2*)(epi + (size_t)(rr + 8) * EPI_STR + pc) =
                        make_float2(acc[mt][nt][2], acc[mt][nt][3]);
                }
            }
        }
        __syncthreads();

        #pragma unroll 4
        for (int it = 0; it < 8; it++) {
            int r = w + it * 8;                     // row within 64
            int jrow = j0 + ph * 64 + r;
            float4 p4 = *(const float4*)(epi + (size_t)r * EPI_STR + (lane & 31) * 4);
            float4 k4 = *(const float4*)(g_K + (size_t)(b256 + jrow) * 512 + n0 + (lane & 31) * 4);
            float v0 = p4.x * q4.x * k4.x;
            float v1 = p4.y * q4.y * k4.y;
            float v2 = p4.z * q4.z * k4.z;
            float v3 = p4.w * q4.w * k4.w;
            *(float4*)(out_e + (size_t)(m0 + ph * 64 + r) * 512 + n0 + (lane & 31) * 4) =
                make_float4(v0, v1, v2, v3);
            float s = (v0 + v1) + (v2 + v3);
            s += __shfl_xor_sync(0xffffffffu, s, 1);
            s += __shfl_xor_sync(0xffffffffu, s, 2);
            s += __shfl_xor_sync(0xffffffffu, s, 4);
            s += __shfl_xor_sync(0xffffffffu, s, 8);
            if ((lane & 15) == 0)
                g_S[((size_t)bi * 256 + jrow) * 8 + head] = s;
        }
        __syncthreads();
    }
}

// =====================================================================
// Pass 3: per (b,i,h): softmax_j(clip(S, -5, 5)), then h_out = w @ V.
// =====================================================================
__global__ __launch_bounds__(256) void softmax_av_kernel(float* __restrict__ out_h)
{
    __shared__ float ws[256];
    __shared__ float wsum[8];
    __shared__ float pacc[4][64];

    int bid = blockIdx.x;
    int hh = bid & 7;
    int bi = bid >> 3;
    int b256 = (bi >> 8) << 8;

    int tid = threadIdx.x;
    int wid = tid >> 5, lane = tid & 31;

    float sv = g_S[(size_t)bi * 2048 + (size_t)tid * 8 + hh];
    sv = fminf(5.f, fmaxf(-5.f, sv));
    float ex = expf(sv);
    ws[tid] = ex;

    float v = ex;
    #pragma unroll
    for (int o = 16; o; o >>= 1) v += __shfl_xor_sync(0xffffffffu, v, o);
    if (lane == 0) wsum[wid] = v;
    __syncthreads();

    float tot = 0.f;
    #pragma unroll
    for (int x = 0; x < 8; x++) tot += wsum[x];
    float inv = 1.f / tot;

    int d = tid & 63, part = tid >> 6;
    const float* Vb = g_V + (size_t)b256 * 512 + hh * 64 + d;
    float a = 0.f;
    int jbase = part * 64;
    #pragma unroll 4
    for (int j = 0; j < 64; j++)
        a += ws[jbase + j] * Vb[(size_t)(jbase + j) * 512];
    pacc[part][d] = a;
    __syncthreads();

    if (part == 0) {
        float r = (pacc[0][d] + pacc[1][d] + pacc[2][d] + pacc[3][d]) * inv;
        out_h[(size_t)bi * 512 + hh * 64 + d] = r;
    }
}

// =====================================================================
extern "C" void kernel_launch(void* const* d_in, const int* in_sizes, int n_in,
                              void* d_out, int out_size)
{
    const float* h  = (const float*)d_in[0];
    const float* e  = (const float*)d_in[1];
    const float* Wq = (const float*)d_in[2];
    const float* Wk = (const float*)d_in[3];
    const float* Wv = (const float*)d_in[4];
    const float* We = (const float*)d_in[5];

    float* out = (float*)d_out;
    float* out_h = out;                              // [4,256,512]
    float* out_e = out + (size_t)BN * CDIM;          // [4,256,256,512]

    dim3 gp(16, 16);
    prep_weT_kernel<<<gp, 256>>>(We);

    dim3 g1(16, 8, 3);
    qkv_kernel<<<g1, 128>>>(h, Wq, Wk, Wv);

    dim3 g2(4, 2048);
    pe_fp16_kernel<<<g2, 256>>>(e, out_e);

    softmax_av_kernel<<<8192, 256>>>(out_h);
}

// round 13
// speedup vs baseline: 1.4058x; 1.1097x over previous
#include <cuda_runtime.h>
#include <cuda_fp16.h>
#include <cstdint>

#define BATCH 4
#define SEQ   256
#define CDIM  512
#define HEADS 8
#define HDIM  64
#define BN    1024        // BATCH*SEQ
#define M2    262144      // BATCH*SEQ*SEQ

// -------- scratch (device globals; no allocation allowed) --------
__device__ float  g_Q[BN * CDIM];           // Q pre-scaled by 1/sqrt(D)=1/8
__device__ float  g_K[BN * CDIM];
__device__ float  g_V[BN * CDIM];
__device__ __half g_WeTh[CDIM * CDIM];      // We transposed [n][k], fp16
__device__ __half g_eh[(size_t)M2 * CDIM];  // e converted to fp16 (268MB)
__device__ float  g_S[(size_t)M2 * HEADS];  // per-head score sums [B,N,N,H]

// ==================== PTX helpers (sm_103 baseline ISA) ====================
__device__ __forceinline__ unsigned f2tf(float x) {
    unsigned u;
    asm("cvt.rna.tf32.f32 %0, %1;" : "=r"(u) : "f"(x));
    return u;
}

__device__ __forceinline__ void mma8(float* c,
                                     unsigned a0, unsigned a1, unsigned a2, unsigned a3,
                                     unsigned b0, unsigned b1) {
    asm volatile(
        "mma.sync.aligned.m16n8k8.row.col.f32.tf32.tf32.f32 "
        "{%0,%1,%2,%3},{%4,%5,%6,%7},{%8,%9},{%0,%1,%2,%3};"
        : "+f"(c[0]), "+f"(c[1]), "+f"(c[2]), "+f"(c[3])
        : "r"(a0), "r"(a1), "r"(a2), "r"(a3), "r"(b0), "r"(b1));
}

__device__ __forceinline__ void mmah(float* c,
                                     unsigned a0, unsigned a1, unsigned a2, unsigned a3,
                                     unsigned b0, unsigned b1) {
    asm volatile(
        "mma.sync.aligned.m16n8k16.row.col.f32.f16.f16.f32 "
        "{%0,%1,%2,%3},{%4,%5,%6,%7},{%8,%9},{%0,%1,%2,%3};"
        : "+f"(c[0]), "+f"(c[1]), "+f"(c[2]), "+f"(c[3])
        : "r"(a0), "r"(a1), "r"(a2), "r"(a3), "r"(b0), "r"(b1));
}

__device__ __forceinline__ void ldsm4(unsigned& r0, unsigned& r1, unsigned& r2, unsigned& r3,
                                      uint32_t addr) {
    asm volatile("ldmatrix.sync.aligned.m8n8.x4.shared.b16 {%0,%1,%2,%3}, [%4];"
                 : "=r"(r0), "=r"(r1), "=r"(r2), "=r"(r3) : "r"(addr));
}

__device__ __forceinline__ void cp16(void* s, const void* g) {
    unsigned ss = (unsigned)__cvta_generic_to_shared(s);
    asm volatile("cp.async.cg.shared.global [%0], [%1], 16;" :: "r"(ss), "l"(g));
}
__device__ __forceinline__ void cp_commit() { asm volatile("cp.async.commit_group;"); }
template <int N>
__device__ __forceinline__ void cp_wait() { asm volatile("cp.async.wait_group %0;" :: "n"(N)); }

__device__ __forceinline__ uint32_t smem_u32(const void* p) {
    uint32_t a;
    asm("{ .reg .u64 t; cvta.to.shared.u64 t, %1; cvt.u32.u64 %0, t; }" : "=r"(a) : "l"(p));
    return a;
}

// =====================================================================
// Prep A: g_WeTh[n][k] = fp16(We[k][n])  (512x512 transpose + convert)
// =====================================================================
__global__ __launch_bounds__(256) void prep_weT_kernel(const float* __restrict__ We)
{
    __shared__ float t[32][33];
    int k0 = blockIdx.x * 32, n0 = blockIdx.y * 32;
    int tx = threadIdx.x & 31, ty = threadIdx.x >> 5;
    #pragma unroll
    for (int yy = 0; yy < 4; yy++) {
        int k = ty + yy * 8;
        t[k][tx] = We[(size_t)(k0 + k) * 512 + n0 + tx];
    }
    __syncthreads();
    #pragma unroll
    for (int yy = 0; yy < 4; yy++) {
        int n = ty + yy * 8;
        g_WeTh[(size_t)(n0 + n) * 512 + k0 + tx] = __float2half_rn(t[tx][n]);
    }
}

// =====================================================================
// Prep B: g_eh = fp16(e)  (pure bandwidth, 8 elems/thread)
// grid=65536, block=256.
// =====================================================================
__global__ __launch_bounds__(256) void prep_eh_kernel(const float* __restrict__ e)
{
    size_t idx = ((size_t)blockIdx.x * 256 + threadIdx.x) * 8;
    float4 a = *(const float4*)(e + idx);
    float4 b = *(const float4*)(e + idx + 4);
    __half2 h0 = __floats2half2_rn(a.x, a.y);
    __half2 h1 = __floats2half2_rn(a.z, a.w);
    __half2 h2 = __floats2half2_rn(b.x, b.y);
    __half2 h3 = __floats2half2_rn(b.z, b.w);
    *(uint4*)(g_eh + idx) = make_uint4(*(unsigned*)&h0, *(unsigned*)&h1,
                                       *(unsigned*)&h2, *(unsigned*)&h3);
}

// =====================================================================
// Pass 1: Q/K/V projections, split-tf32 (3-mma) for ~fp32 accuracy.
// =====================================================================
__global__ __launch_bounds__(128) void qkv_kernel(
    const float* __restrict__ hmat,
    const float* __restrict__ Wq,
    const float* __restrict__ Wk,
    const float* __restrict__ Wv)
{
    __shared__ float Ah[64][36], Al[64][36];
    __shared__ float Bh[32][72], Bl[32][72];

    int z = blockIdx.z;
    const float* W = (z == 0) ? Wq : ((z == 1) ? Wk : Wv);
    float* Out = (z == 0) ? g_Q : ((z == 1) ? g_K : g_V);
    float scale = (z == 0) ? 0.125f : 1.0f;

    int m0 = blockIdx.x * 64, n0 = blockIdx.y * 64;
    int tid = threadIdx.x;
    int w = tid >> 5, lane = tid & 31, g = lane >> 2, q = lane & 3;
    int wr = (w >> 1) * 32, wc = (w & 1) * 32;

    float acc[2][4][4] = {};

    for (int k0 = 0; k0 < 512; k0 += 32) {
        #pragma unroll
        for (int it = 0; it < 4; it++) {
            int f = tid + it * 128;
            int r = f >> 3, c4 = (f & 7) * 4;
            float4 x = *(const float4*)(hmat + (size_t)(m0 + r) * 512 + k0 + c4);
            float hx = __uint_as_float(f2tf(x.x));
            float hy = __uint_as_float(f2tf(x.y));
            float hz = __uint_as_float(f2tf(x.z));
            float hw = __uint_as_float(f2tf(x.w));
            Ah[r][c4 + 0] = hx; Ah[r][c4 + 1] = hy; Ah[r][c4 + 2] = hz; Ah[r][c4 + 3] = hw;
            Al[r][c4 + 0] = __uint_as_float(f2tf(x.x - hx));
            Al[r][c4 + 1] = __uint_as_float(f2tf(x.y - hy));
            Al[r][c4 + 2] = __uint_as_float(f2tf(x.z - hz));
            Al[r][c4 + 3] = __uint_as_float(f2tf(x.w - hw));
        }
        #pragma unroll
        for (int it = 0; it < 4; it++) {
            int f = tid + it * 128;
            int k = f >> 4, c4 = (f & 15) * 4;
            float4 x = *(const float4*)(W + (size_t)(k0 + k) * 512 + n0 + c4);
            float hx = __uint_as_float(f2tf(x.x));
            float hy = __uint_as_float(f2tf(x.y));
            float hz = __uint_as_float(f2tf(x.z));
            float hw = __uint_as_float(f2tf(x.w));
            Bh[k][c4 + 0] = hx; Bh[k][c4 + 1] = hy; Bh[k][c4 + 2] = hz; Bh[k][c4 + 3] = hw;
            Bl[k][c4 + 0] = __uint_as_float(f2tf(x.x - hx));
            Bl[k][c4 + 1] = __uint_as_float(f2tf(x.y - hy));
            Bl[k][c4 + 2] = __uint_as_float(f2tf(x.z - hz));
            Bl[k][c4 + 3] = __uint_as_float(f2tf(x.w - hw));
        }
        __syncthreads();

        #pragma unroll
        for (int kt = 0; kt < 4; kt++) {
            unsigned ah[2][4], al[2][4];
            #pragma unroll
            for (int m = 0; m < 2; m++) {
                int r = wr + m * 16 + g;
                int kk = kt * 8 + q;
                ah[m][0] = __float_as_uint(Ah[r][kk]);
                ah[m][1] = __float_as_uint(Ah[r + 8][kk]);
                ah[m][2] = __float_as_uint(Ah[r][kk + 4]);
                ah[m][3] = __float_as_uint(Ah[r + 8][kk + 4]);
                al[m][0] = __float_as_uint(Al[r][kk]);
                al[m][1] = __float_as_uint(Al[r + 8][kk]);
                al[m][2] = __float_as_uint(Al[r][kk + 4]);
                al[m][3] = __float_as_uint(Al[r + 8][kk + 4]);
            }
            unsigned bh[4][2], bl[4][2];
            #pragma unroll
            for (int nt = 0; nt < 4; nt++) {
                int cc = wc + nt * 8 + g;
                bh[nt][0] = __float_as_uint(Bh[kt * 8 + q][cc]);
                bh[nt][1] = __float_as_uint(Bh[kt * 8 + q + 4][cc]);
                bl[nt][0] = __float_as_uint(Bl[kt * 8 + q][cc]);
                bl[nt][1] = __float_as_uint(Bl[kt * 8 + q + 4][cc]);
            }
            #pragma unroll
            for (int m = 0; m < 2; m++)
                #pragma unroll
                for (int nt = 0; nt < 4; nt++) {
                    mma8(acc[m][nt], ah[m][0], ah[m][1], ah[m][2], ah[m][3], bh[nt][0], bh[nt][1]);
                    mma8(acc[m][nt], ah[m][0], ah[m][1], ah[m][2], ah[m][3], bl[nt][0], bl[nt][1]);
                    mma8(acc[m][nt], al[m][0], al[m][1], al[m][2], al[m][3], bh[nt][0], bh[nt][1]);
                }
        }
        __syncthreads();
    }

    #pragma unroll
    for (int m = 0; m < 2; m++) {
        int r0 = m0 + wr + m * 16 + g;
        #pragma unroll
        for (int nt = 0; nt < 4; nt++) {
            int c0 = n0 + wc + nt * 8 + 2 * q;
            *(float2*)(Out + (size_t)r0 * 512 + c0) =
                make_float2(acc[m][nt][0] * scale, acc[m][nt][1] * scale);
            *(float2*)(Out + (size_t)(r0 + 8) * 512 + c0) =
                make_float2(acc[m][nt][2] * scale, acc[m][nt][3] * scale);
        }
    }
}

// =====================================================================
// Pass 2 (fp16 HMMA, 3-stage cp.async pipeline):
// pe = e @ We. CTA tile 128(m) x 128(n), K-chunk 64 (8 chunks), both
// operands fp16 via cp.async (A from pre-converted g_eh, B from g_WeTh).
// Rows 144B (data 128B) -> ldsm conflict-free. Warp grid 2(m)x4(n),
// warp tile 64x32, m16n8k16. ONE __syncthreads per chunk.
// grid=(4, 2048): 4 n-CTAs of an m-tile launch-adjacent -> e L2 reuse.
// Epilogue: two 64-row phases staged via smem (aliases stage 0) ->
// val = pe*q*k -> coalesced e_out store + per-head row sums into g_S.
// Dynamic smem 108KB -> 2 CTAs/SM.
// =====================================================================
#define P_STR    144
#define P_TILE   (128 * P_STR)          // 18432
#define P_STAGE  (2 * P_TILE)           // 36864 (A then B)
#define PE_SMEM  (3 * P_STAGE)          // 110592
#define EPI_STR  132                    // 64*132*4 = 33792 (aliases stage 0)

__global__ __launch_bounds__(256, 2) void pe_fp16_kernel(float* __restrict__ out_e)
{
    extern __shared__ char smem[];
    uint32_t sb = smem_u32(smem);

    int tid = threadIdx.x;
    int w = tid >> 5, lane = tid & 31, g = lane >> 2, q = lane & 3;
    int wm = (w >> 2) * 64;     // warp m-offset: 0 or 64
    int wn = (w & 3) * 32;      // warp n-offset: 0,32,64,96

    int n0 = blockIdx.x * 128;
    int m0 = blockIdx.y * 128;
    int b = m0 >> 16;
    int i = (m0 >> 8) & 255;
    int j0 = m0 & 255;
    int bi = b * 256 + i;
    int b256 = b * 256;

    // shared ldsm lane addressing: (lane&15)=row-in-16, (lane>>4)=16B half of k16
    uint32_t lbase = sb + (uint32_t)((lane & 15) * P_STR + (lane >> 4) * 16);

    float acc[4][4][4] = {};

    auto load_stage = [&](int kc, int slot) {
        char* da = smem + slot * P_STAGE;
        char* db = da + P_TILE;
        #pragma unroll
        for (int it = 0; it < 4; it++) {
            int idx = tid + it * 256;
            int row = idx >> 3, seg = idx & 7;
            cp16(da + row * P_STR + seg * 16,
                 g_eh + (size_t)(m0 + row) * 512 + kc * 64 + seg * 8);
            cp16(db + row * P_STR + seg * 16,
                 g_WeTh + (size_t)(n0 + row) * 512 + kc * 64 + seg * 8);
        }
        cp_commit();
    };

    auto compute = [&](int slot) {
        uint32_t Ab = lbase + slot * P_STAGE + wm * P_STR;
        uint32_t Bb = lbase + slot * P_STAGE + P_TILE + wn * P_STR;
        #pragma unroll
        for (int kt = 0; kt < 4; kt++) {
            unsigned bf[2][4];
            #pragma unroll
            for (int pr = 0; pr < 2; pr++)
                ldsm4(bf[pr][0], bf[pr][1], bf[pr][2], bf[pr][3],
                      Bb + pr * (16 * P_STR) + kt * 32);
            #pragma unroll
            for (int mt = 0; mt < 4; mt++) {
                unsigned a0, a1, a2, a3;
                ldsm4(a0, a1, a2, a3, Ab + mt * (16 * P_STR) + kt * 32);
                mmah(acc[mt][0], a0, a1, a2, a3, bf[0][0], bf[0][2]);
                mmah(acc[mt][1], a0, a1, a2, a3, bf[0][1], bf[0][3]);
                mmah(acc[mt][2], a0, a1, a2, a3, bf[1][0], bf[1][2]);
                mmah(acc[mt][3], a0, a1, a2, a3, bf[1][1], bf[1][3]);
            }
        }
    };

    // prologue: stages 0,1
    load_stage(0, 0);
    load_stage(1, 1);

    #pragma unroll 1
    for (int c = 0; c < 8; c++) {
        if (c < 7) cp_wait<1>(); else cp_wait<0>();
        __syncthreads();                       // chunk c visible to all warps;
                                               // all warps done computing c-1
        if (c + 2 < 8) load_stage(c + 2, (c + 2) % 3);  // overwrites slot of c-1
        compute(c % 3);
    }
    __syncthreads();

    // ---- epilogue: two 64-row phases staged through smem (stage 0) ----
    float* epi = (float*)smem;
    float4 q4 = *(const float4*)(g_Q + (size_t)bi * 512 + n0 + lane * 4);
    int head = (n0 >> 6) + (lane >> 4);

    #pragma unroll 1
    for (int ph = 0; ph < 2; ph++) {
        if (wm == ph * 64) {
            #pragma unroll
            for (int mt = 0; mt < 4; mt++) {
                int rr = mt * 16 + g;
                #pragma unroll
                for (int nt = 0; nt < 4; nt++) {
                    int pc = wn + nt * 8 + 2 * q;
                    *(float2*)(epi + (size_t)rr * EPI_STR + pc) =
                        make_float2(acc[mt][nt][0], acc[mt][nt][1]);
                    *(float2*)(epi + (size_t)(rr + 8) * EPI_STR + pc) =
                        make_float2(acc[mt][nt][2], acc[mt][nt][3]);
                }
            }
        }
        __syncthreads();

        #pragma unroll 4
        for (int it = 0; it < 8; it++) {
            int r = w + it * 8;                     // row within 64
            int jrow = j0 + ph * 64 + r;
            float4 p4 = *(const float4*)(epi + (size_t)r * EPI_STR + lane * 4);
            float4 k4 = *(const float4*)(g_K + (size_t)(b256 + jrow) * 512 + n0 + lane * 4);
            float v0 = p4.x * q4.x * k4.x;
            float v1 = p4.y * q4.y * k4.y;
            float v2 = p4.z * q4.z * k4.z;
            float v3 = p4.w * q4.w * k4.w;
            *(float4*)(out_e + (size_t)(m0 + ph * 64 + r) * 512 + n0 + lane * 4) =
                make_float4(v0, v1, v2, v3);
            float s = (v0 + v1) + (v2 + v3);
            s += __shfl_xor_sync(0xffffffffu, s, 1);
            s += __shfl_xor_sync(0xffffffffu, s, 2);
            s += __shfl_xor_sync(0xffffffffu, s, 4);
            s += __shfl_xor_sync(0xffffffffu, s, 8);
            if ((lane & 15) == 0)
                g_S[((size_t)bi * 256 + jrow) * 8 + head] = s;
        }
        __syncthreads();
    }
}

// =====================================================================
// Pass 3: per (b,i,h): softmax_j(clip(S, -5, 5)), then h_out = w @ V.
// =====================================================================
__global__ __launch_bounds__(256) void softmax_av_kernel(float* __restrict__ out_h)
{
    __shared__ float ws[256];
    __shared__ float wsum[8];
    __shared__ float pacc[4][64];

    int bid = blockIdx.x;
    int hh = bid & 7;
    int bi = bid >> 3;
    int b256 = (bi >> 8) << 8;

    int tid = threadIdx.x;
    int wid = tid >> 5, lane = tid & 31;

    float sv = g_S[(size_t)bi * 2048 + (size_t)tid * 8 + hh];
    sv = fminf(5.f, fmaxf(-5.f, sv));
    float ex = expf(sv);
    ws[tid] = ex;

    float v = ex;
    #pragma unroll
    for (int o = 16; o; o >>= 1) v += __shfl_xor_sync(0xffffffffu, v, o);
    if (lane == 0) wsum[wid] = v;
    __syncthreads();

    float tot = 0.f;
    #pragma unroll
    for (int x = 0; x < 8; x++) tot += wsum[x];
    float inv = 1.f / tot;

    int d = tid & 63, part = tid >> 6;
    const float* Vb = g_V + (size_t)b256 * 512 + hh * 64 + d;
    float a = 0.f;
    int jbase = part * 64;
    #pragma unroll 4
    for (int j = 0; j < 64; j++)
        a += ws[jbase + j] * Vb[(size_t)(jbase + j) * 512];
    pacc[part][d] = a;
    __syncthreads();

    if (part == 0) {
        float r = (pacc[0][d] + pacc[1][d] + pacc[2][d] + pacc[3][d]) * inv;
        out_h[(size_t)bi * 512 + hh * 64 + d] = r;
    }
}

// =====================================================================
extern "C" void kernel_launch(void* const* d_in, const int* in_sizes, int n_in,
                              void* d_out, int out_size)
{
    const float* h  = (const float*)d_in[0];
    const float* e  = (const float*)d_in[1];
    const float* Wq = (const float*)d_in[2];
    const float* Wk = (const float*)d_in[3];
    const float* Wv = (const float*)d_in[4];
    const float* We = (const float*)d_in[5];

    float* out = (float*)d_out;
    float* out_h = out;                              // [4,256,512]
    float* out_e = out + (size_t)BN * CDIM;          // [4,256,256,512]

    dim3 gp(16, 16);
    prep_weT_kernel<<<gp, 256>>>(We);

    prep_eh_kernel<<<65536, 256>>>(e);

    dim3 g1(16, 8, 3);
    qkv_kernel<<<g1, 128>>>(h, Wq, Wk, Wv);

    cudaFuncSetAttribute(pe_fp16_kernel, cudaFuncAttributeMaxDynamicSharedMemorySize, PE_SMEM);
    dim3 g2(4, 2048);
    pe_fp16_kernel<<<g2, 256, PE_SMEM>>>(out_e);

    softmax_av_kernel<<<8192, 256>>>(out_h);
}